// round 15
// baseline (speedup 1.0000x reference)
#include <cuda_runtime.h>
#include <cstdint>

#define SS 7
#define NCLS 20
#define NN 98            // S*S*B
#define NP 128           // padded box count
#define CONF_TH 0.1f
#define NTHREADS 640     // 20 warps, warp = class
#define CH 30            // B*5 + NC
#define PRED_PER_BATCH (SS*SS*CH)   // 1470
#define SCORE_BASE 0x3DCCCCCDu      // float bits of 0.1f

typedef unsigned u32;
typedef unsigned long long u64;

__global__ void __launch_bounds__(NTHREADS, 3)
yolo_nms_kernel(const float* __restrict__ pred, float* __restrict__ out)
{
    __shared__ float  s_pred[PRED_PER_BATCH + 2];
    __shared__ float4 s_box[NP];         // (x1,y1,x2,y2); NaN for pads
    __shared__ float  s_area[NP];        // NaN for pads
    __shared__ u32    s_key[NCLS][NP];   // 0 invalid/pad; ((bits-BASE)<<7)|(127-i)
    __shared__ uint4  s_sup[NN];         // row p: IoU(p,q) > 0.5 bitmask
    __shared__ u32    s_V[4];            // box valid in >=1 class (exact union)

    const int batch = blockIdx.x;
    const int tid   = threadIdx.x;
    const int wid   = tid >> 5;          // = class
    const int lane  = tid & 31;
    const unsigned FULL = 0xffffffffu;
    const u32 lane_bit = 1u << lane;

    // ---- A: stage pred (float2, coalesced; 1470 floats = 735 f2) ----
    {
        const float2* pb2 = reinterpret_cast<const float2*>(pred + (size_t)batch * PRED_PER_BATCH);
        float2* sp2 = reinterpret_cast<float2*>(s_pred);
        if (tid < 735) {
            sp2[tid] = pb2[tid];
            const int i2 = tid + NTHREADS;          // 640..734 covered by tid<95
            if (i2 < 735) sp2[i2] = pb2[i2];
        }
    }
    __syncthreads();

    // ---- B1 (warps 0-3): decode boxes + global-validity mask V ----
    // V bit i: box i valid in SOME class. Exact: exists c with cls_c*bconf
    // > 0.1  <=>  (max_c cls_c)*bconf > 0.1 (fp32 mul by >=0 is monotone,
    // rounding is monotone, so max commutes with the product). Rows of
    // s_sup are only read for active boxes (subset of V) -> skipped rows'
    // stale contents are never consulted.
    if (tid < NP) {
        const int i = tid;
        bool gvalid = false;
        if (i < NN) {
            const int cell = i >> 1, b = i & 1;
            const float* p = s_pred + cell * CH + b * 5;
            const float rowf = (float)(cell / SS);
            const float colf = (float)(cell % SS);
            const float cs = 1.0f / (float)SS;
            float cx = (p[0] + rowf) * cs;
            float cy = (p[1] + colf) * cs;
            float hw = p[2] * 0.5f, hh = p[3] * 0.5f;
            float x1 = fminf(fmaxf(cx - hw, 0.0f), 1.0f);
            float y1 = fminf(fmaxf(cy - hh, 0.0f), 1.0f);
            float x2 = fminf(fmaxf(cx + hw, 0.0f), 1.0f);
            float y2 = fminf(fmaxf(cy + hh, 0.0f), 1.0f);
            s_box[i] = make_float4(x1, y1, x2, y2);
            s_area[i] = (x2 - x1) * (y2 - y1);
            const float* cp = s_pred + cell * CH + 10;
            float mc = cp[0];
            #pragma unroll
            for (int c = 1; c < NCLS; c++) mc = fmaxf(mc, cp[c]);
            gvalid = (mc * p[4] > CONF_TH);
        } else {
            const float qn = __uint_as_float(0x7FC00000u);   // NaN
            s_box[i] = make_float4(qn, qn, qn, qn);
            s_area[i] = qn;                                  // sup bit false, no predicate
        }
        const u32 vm = __ballot_sync(FULL, gvalid);
        if (lane == 0) s_V[wid] = vm;                        // wid = i>>5 here
    }

    // ---- B2: keys (warp = class); zero for invalid and pads ----
    // key preserves exact reference order incl. tie -> lower index:
    // valid scores in (0.1, 1] -> (bits - BASE) < 2^25 -> <<7 fits u32.
    {
        const int c = wid;
        #pragma unroll
        for (int j = 0; j < 4; j++) {
            const int i = lane + 32 * j;
            u32 key = 0;
            if (i < NN) {
                const int cell = i >> 1, b = i & 1;
                const float s = s_pred[cell * CH + 10 + c] * s_pred[cell * CH + b * 5 + 4];
                if (s > CONF_TH)
                    key = ((__float_as_uint(s) - SCORE_BASE) << 7) | (u32)(127 - i);
            }
            s_key[c][i] = key;
        }
    }
    __syncthreads();

    // ---- C: suppression bitmasks; warp w owns rows p = w + 20t ----
    // bit(q): IoU(p,q) > 0.5  <=>  3*inter > area_p + area_q (division-free,
    // symmetric; empirically validated form). NaN pad areas -> false bits.
    // Rows of globally-invalid boxes are skipped (uniform branch): their
    // sup row can never be read by D.
    {
        float4 qb[4]; float qa[4];
        #pragma unroll
        for (int j = 0; j < 4; j++) {
            const int q = lane + 32 * j;
            qb[j] = s_box[q]; qa[j] = s_area[q];
        }
        #pragma unroll
        for (int t = 0; t < 5; t++) {
            const int p = wid + 20 * t;
            if (p < NN && (s_V[p >> 5] & (1u << (p & 31)))) {
                const float4 a = s_box[p];
                const float ap = s_area[p];
                u32 m[4];
                #pragma unroll
                for (int j = 0; j < 4; j++) {
                    float w = fminf(a.z, qb[j].z) - fmaxf(a.x, qb[j].x);
                    float h = fminf(a.w, qb[j].w) - fmaxf(a.y, qb[j].y);
                    w = fmaxf(w, 0.0f); h = fmaxf(h, 0.0f);
                    const float inter = w * h;
                    m[j] = __ballot_sync(FULL, 3.0f * inter > ap + qa[j]);
                }
                if (lane == 0) s_sup[p] = make_uint4(m[0], m[1], m[2], m[3]);
            }
        }
    }
    __syncthreads();

    // ---- D: iterated local-max NMS (exactly == sequential greedy) ----
    // FROZEN (R9 form): full-max scan pipelines its LDS; early-exit and
    // atomics variants both regressed (R12/R13). Keep every active box
    // whose key beats all active neighbors, remove kept + suppressed,
    // repeat. act[w] warp-uniform -> uniform dead-word skip.
    u32 keep0 = 0, keep1 = 0, keep2 = 0, keep3 = 0;
    {
        const int c = wid;
        u32 act[4], k[4];
        #pragma unroll
        for (int w = 0; w < 4; w++) {
            k[w] = s_key[c][lane + 32 * w];
            act[w] = __ballot_sync(FULL, k[w] != 0u);
        }
        for (int pass = 0; pass < NN; ++pass) {
            if (!(act[0] | act[1] | act[2] | act[3])) break;
            u32 lm[4];
            #pragma unroll
            for (int w = 0; w < 4; w++) {
                u32 lmw = 0;
                if (act[w]) {                        // uniform skip
                    bool is_lm = false;
                    if (act[w] & lane_bit) {
                        const int i = lane + 32 * w;
                        const uint4 row = s_sup[i];
                        u32 n0 = row.x & act[0];
                        u32 n1 = row.y & act[1];
                        u32 n2 = row.z & act[2];
                        u32 n3 = row.w & act[3];
                        if (w == 0) n0 &= ~lane_bit;
                        else if (w == 1) n1 &= ~lane_bit;
                        else if (w == 2) n2 &= ~lane_bit;
                        else n3 &= ~lane_bit;
                        u32 mk = 0;
                        while (n0) { const int q = __ffs(n0) - 1;  n0 &= n0 - 1; mk = max(mk, s_key[c][q]); }
                        while (n1) { const int q = __ffs(n1) + 31; n1 &= n1 - 1; mk = max(mk, s_key[c][q]); }
                        while (n2) { const int q = __ffs(n2) + 63; n2 &= n2 - 1; mk = max(mk, s_key[c][q]); }
                        while (n3) { const int q = __ffs(n3) + 95; n3 &= n3 - 1; mk = max(mk, s_key[c][q]); }
                        is_lm = (k[w] > mk);
                    }
                    lmw = __ballot_sync(FULL, is_lm);
                }
                lm[w] = lmw;
            }
            keep0 |= lm[0]; keep1 |= lm[1]; keep2 |= lm[2]; keep3 |= lm[3];
            #pragma unroll
            for (int w = 0; w < 4; w++) {
                if (act[w]) {                        // uniform skip
                    bool rem = false;
                    if (act[w] & lane_bit) {
                        const uint4 row = s_sup[lane + 32 * w];
                        rem = ((row.x & lm[0]) | (row.y & lm[1]) |
                               (row.z & lm[2]) | (row.w & lm[3])) != 0u;
                        // kept boxes self-remove via their own row's self bit
                    }
                    act[w] &= ~__ballot_sync(FULL, rem);
                }
            }
        }
    }

    // ---- E: output, warp = class, float4 stores, multiply-by-kf ----
    // Row per box: [x1,y1,x2,y2,score,keep]*kf. 2 boxes = 3 float4.
    // score reconstructed from key: (key>>7)+BASE; key==0 -> 0.1f*0 = 0.
    // Iterations 0..3 have v4 <= 127 < 147: no bounds check needed.
    {
        const int c = wid;
        const u64 kpLo = (u64)keep0 | ((u64)keep1 << 32);
        const u64 kpHi = (u64)keep2 | ((u64)keep3 << 32);
        float4* op = reinterpret_cast<float4*>(out + ((size_t)batch * NCLS + c) * (NN * 6));
        #pragma unroll
        for (int it = 0; it < 5; ++it) {
            const int v4 = lane + 32 * it;
            if (it == 4 && v4 >= 147) break;
            const int g = v4 / 3;
            const int part = v4 - 3 * g;
            const int t = 2 * g;
            const float kf0 = ((((t < 64) ? (kpLo >> t) : (kpHi >> (t - 64))) & 1ull) != 0ull) ? 1.0f : 0.0f;
            const float kf1 = ((((t + 1 < 64) ? (kpLo >> (t + 1)) : (kpHi >> (t - 63))) & 1ull) != 0ull) ? 1.0f : 0.0f;
            float4 v;
            if (part == 0) {
                const float4 b0 = s_box[t];
                v = make_float4(b0.x * kf0, b0.y * kf0, b0.z * kf0, b0.w * kf0);
            } else if (part == 1) {
                const float sc0 = __uint_as_float((s_key[c][t] >> 7) + SCORE_BASE);
                const float4 b1 = s_box[t + 1];
                v = make_float4(sc0 * kf0, kf0, b1.x * kf1, b1.y * kf1);
            } else {
                const float4 b1 = s_box[t + 1];
                const float sc1 = __uint_as_float((s_key[c][t + 1] >> 7) + SCORE_BASE);
                v = make_float4(b1.z * kf1, b1.w * kf1, sc1 * kf1, kf1);
            }
            op[v4] = v;
        }
    }
}

extern "C" void kernel_launch(void* const* d_in, const int* in_sizes, int n_in,
                              void* d_out, int out_size)
{
    const float* pred = (const float*)d_in[0];
    float* out = (float*)d_out;
    const int bs = in_sizes[0] / PRED_PER_BATCH;
    yolo_nms_kernel<<<bs, NTHREADS>>>(pred, out);
}

// round 16
// speedup vs baseline: 1.0788x; 1.0788x over previous
#include <cuda_runtime.h>
#include <cstdint>

#define SS 7
#define NCLS 20
#define NN 98            // S*S*B
#define NP 128           // padded box count
#define NROWS 100        // sup rows incl. 2 pad rows (warps 18/19 @ t=4)
#define CONF_TH 0.1f
#define NTHREADS 640     // 20 warps, warp = class
#define CH 30            // B*5 + NC
#define PRED_PER_BATCH (SS*SS*CH)   // 1470
#define SCORE_BASE 0x3DCCCCCDu      // float bits of 0.1f

typedef unsigned u32;
typedef unsigned long long u64;

__global__ void __launch_bounds__(NTHREADS, 3)
yolo_nms_kernel(const float* __restrict__ pred, float* __restrict__ out)
{
    __shared__ float  s_pred[PRED_PER_BATCH + 2];
    __shared__ float4 s_box[NP];         // (x1,y1,x2,y2); NaN for pads
    __shared__ float  s_area[NP];        // NaN for pads
    __shared__ u32    s_key[NCLS][NP];   // 0 invalid/pad; ((bits-BASE)<<7)|(127-i)
    __shared__ uint4  s_sup[NROWS];      // row p: IoU(p,q) > 0.5 bitmask

    const int batch = blockIdx.x;
    const int tid   = threadIdx.x;
    const int wid   = tid >> 5;          // = class
    const int lane  = tid & 31;
    const unsigned FULL = 0xffffffffu;
    const u32 lane_bit = 1u << lane;

    // ---- A: stage pred (float2, coalesced; 1470 floats = 735 f2) ----
    {
        const float2* pb2 = reinterpret_cast<const float2*>(pred + (size_t)batch * PRED_PER_BATCH);
        float2* sp2 = reinterpret_cast<float2*>(s_pred);
        if (tid < 735) {
            sp2[tid] = pb2[tid];
            const int i2 = tid + NTHREADS;          // 640..734 covered by tid<95
            if (i2 < 735) sp2[i2] = pb2[i2];
        }
    }
    __syncthreads();

    // ---- B1: decode boxes -> AoS float4 + area; NaN pads for i >= NN ----
    if (tid < NP) {
        const int i = tid;
        if (i < NN) {
            const int cell = i >> 1, b = i & 1;
            const float* p = s_pred + cell * CH + b * 5;
            const float rowf = (float)(cell / SS);
            const float colf = (float)(cell % SS);
            const float cs = 1.0f / (float)SS;
            float cx = (p[0] + rowf) * cs;
            float cy = (p[1] + colf) * cs;
            float hw = p[2] * 0.5f, hh = p[3] * 0.5f;
            float x1 = fminf(fmaxf(cx - hw, 0.0f), 1.0f);
            float y1 = fminf(fmaxf(cy - hh, 0.0f), 1.0f);
            float x2 = fminf(fmaxf(cx + hw, 0.0f), 1.0f);
            float y2 = fminf(fmaxf(cy + hh, 0.0f), 1.0f);
            s_box[i] = make_float4(x1, y1, x2, y2);
            s_area[i] = (x2 - x1) * (y2 - y1);
        } else {
            const float qn = __uint_as_float(0x7FC00000u);   // NaN
            s_box[i] = make_float4(qn, qn, qn, qn);
            s_area[i] = qn;                                  // sup bit false, no predicate
        }
    }

    // ---- B2: keys (warp = class); zero for invalid and pads ----
    // key preserves exact reference order incl. tie -> lower index:
    // valid scores in (0.1, 1] -> (bits - BASE) < 2^25 -> <<7 fits u32.
    {
        const int c = wid;
        #pragma unroll
        for (int j = 0; j < 4; j++) {
            const int i = lane + 32 * j;
            u32 key = 0;
            if (i < NN) {
                const int cell = i >> 1, b = i & 1;
                const float s = s_pred[cell * CH + 10 + c] * s_pred[cell * CH + b * 5 + 4];
                if (s > CONF_TH)
                    key = ((__float_as_uint(s) - SCORE_BASE) << 7) | (u32)(127 - i);
            }
            s_key[c][i] = key;
        }
    }
    __syncthreads();

    // ---- C: suppression bitmasks; warp w owns rows p = w + 20t ----
    // bit(q): IoU(p,q) > 0.5  <=>  3*inter > area_p + area_q (division-free,
    // symmetric; empirically validated form). NaN pad areas -> false bits.
    // No row guard: rows 98/99 (NaN boxes) produce all-false masks into
    // pad slots of s_sup that D can never read (keys force i < NN).
    {
        float4 qb[4]; float qa[4];
        #pragma unroll
        for (int j = 0; j < 4; j++) {
            const int q = lane + 32 * j;
            qb[j] = s_box[q]; qa[j] = s_area[q];
        }
        #pragma unroll
        for (int t = 0; t < 5; t++) {
            const int p = wid + 20 * t;
            const float4 a = s_box[p];
            const float ap = s_area[p];
            u32 m[4];
            #pragma unroll
            for (int j = 0; j < 4; j++) {
                float w = fminf(a.z, qb[j].z) - fmaxf(a.x, qb[j].x);
                float h = fminf(a.w, qb[j].w) - fmaxf(a.y, qb[j].y);
                w = fmaxf(w, 0.0f); h = fmaxf(h, 0.0f);
                const float inter = w * h;
                m[j] = __ballot_sync(FULL, 3.0f * inter > ap + qa[j]);
            }
            if (lane == 0) s_sup[p] = make_uint4(m[0], m[1], m[2], m[3]);
        }
    }
    __syncthreads();

    // ---- D: iterated local-max NMS (exactly == sequential greedy) ----
    // FROZEN (R9 form; early-exit, u64 scan, smem atomics, isolation
    // masks all regressed — R12/R13/R15). Keep every active box whose
    // key beats all active neighbors, remove kept + suppressed, repeat.
    // act[w] warp-uniform -> uniform dead-word skip. Full-max scan keeps
    // neighbor-key LDS off the loop-condition path so they pipeline.
    u32 keep0 = 0, keep1 = 0, keep2 = 0, keep3 = 0;
    {
        const int c = wid;
        u32 act[4], k[4];
        #pragma unroll
        for (int w = 0; w < 4; w++) {
            k[w] = s_key[c][lane + 32 * w];
            act[w] = __ballot_sync(FULL, k[w] != 0u);
        }
        for (int pass = 0; pass < NN; ++pass) {
            if (!(act[0] | act[1] | act[2] | act[3])) break;
            u32 lm[4];
            #pragma unroll
            for (int w = 0; w < 4; w++) {
                u32 lmw = 0;
                if (act[w]) {                        // uniform skip
                    bool is_lm = false;
                    if (act[w] & lane_bit) {
                        const int i = lane + 32 * w;
                        const uint4 row = s_sup[i];
                        u32 n0 = row.x & act[0];
                        u32 n1 = row.y & act[1];
                        u32 n2 = row.z & act[2];
                        u32 n3 = row.w & act[3];
                        if (w == 0) n0 &= ~lane_bit;
                        else if (w == 1) n1 &= ~lane_bit;
                        else if (w == 2) n2 &= ~lane_bit;
                        else n3 &= ~lane_bit;
                        u32 mk = 0;
                        while (n0) { const int q = __ffs(n0) - 1;  n0 &= n0 - 1; mk = max(mk, s_key[c][q]); }
                        while (n1) { const int q = __ffs(n1) + 31; n1 &= n1 - 1; mk = max(mk, s_key[c][q]); }
                        while (n2) { const int q = __ffs(n2) + 63; n2 &= n2 - 1; mk = max(mk, s_key[c][q]); }
                        while (n3) { const int q = __ffs(n3) + 95; n3 &= n3 - 1; mk = max(mk, s_key[c][q]); }
                        is_lm = (k[w] > mk);
                    }
                    lmw = __ballot_sync(FULL, is_lm);
                }
                lm[w] = lmw;
            }
            keep0 |= lm[0]; keep1 |= lm[1]; keep2 |= lm[2]; keep3 |= lm[3];
            #pragma unroll
            for (int w = 0; w < 4; w++) {
                if (act[w]) {                        // uniform skip
                    bool rem = false;
                    if (act[w] & lane_bit) {
                        const uint4 row = s_sup[lane + 32 * w];
                        rem = ((row.x & lm[0]) | (row.y & lm[1]) |
                               (row.z & lm[2]) | (row.w & lm[3])) != 0u;
                        // kept boxes self-remove via their own row's self bit
                    }
                    act[w] &= ~__ballot_sync(FULL, rem);
                }
            }
        }
    }

    // ---- E: output, warp = class, float4 stores, multiply-by-kf ----
    // Row per box: [x1,y1,x2,y2,score,keep]*kf. 2 boxes = 3 float4.
    // score reconstructed from key: (key>>7)+BASE; key==0 -> 0.1f*0 = 0.
    // Iterations 0..3 have v4 <= 127 < 147: no bounds check needed.
    {
        const int c = wid;
        const u64 kpLo = (u64)keep0 | ((u64)keep1 << 32);
        const u64 kpHi = (u64)keep2 | ((u64)keep3 << 32);
        float4* op = reinterpret_cast<float4*>(out + ((size_t)batch * NCLS + c) * (NN * 6));
        #pragma unroll
        for (int it = 0; it < 5; ++it) {
            const int v4 = lane + 32 * it;
            if (it == 4 && v4 >= 147) break;
            const int g = v4 / 3;
            const int part = v4 - 3 * g;
            const int t = 2 * g;
            const float kf0 = ((((t < 64) ? (kpLo >> t) : (kpHi >> (t - 64))) & 1ull) != 0ull) ? 1.0f : 0.0f;
            const float kf1 = ((((t + 1 < 64) ? (kpLo >> (t + 1)) : (kpHi >> (t - 63))) & 1ull) != 0ull) ? 1.0f : 0.0f;
            float4 v;
            if (part == 0) {
                const float4 b0 = s_box[t];
                v = make_float4(b0.x * kf0, b0.y * kf0, b0.z * kf0, b0.w * kf0);
            } else if (part == 1) {
                const float sc0 = __uint_as_float((s_key[c][t] >> 7) + SCORE_BASE);
                const float4 b1 = s_box[t + 1];
                v = make_float4(sc0 * kf0, kf0, b1.x * kf1, b1.y * kf1);
            } else {
                const float4 b1 = s_box[t + 1];
                const float sc1 = __uint_as_float((s_key[c][t + 1] >> 7) + SCORE_BASE);
                v = make_float4(b1.z * kf1, b1.w * kf1, sc1 * kf1, kf1);
            }
            op[v4] = v;
        }
    }
}

extern "C" void kernel_launch(void* const* d_in, const int* in_sizes, int n_in,
                              void* d_out, int out_size)
{
    const float* pred = (const float*)d_in[0];
    float* out = (float*)d_out;
    const int bs = in_sizes[0] / PRED_PER_BATCH;
    yolo_nms_kernel<<<bs, NTHREADS>>>(pred, out);
}